// round 15
// baseline (speedup 1.0000x reference)
#include <cuda_runtime.h>

#define N_NODES 200000
#define N_EDGES 1600000
#define F_IN    32
#define HDIM    24
#define HPAD    32             // padded row stride (floats): 128B, line-aligned
#define ELL_CAP 64             // max in-degree capacity (Poisson(8): P(>64) ~ 0)

// Scratch (allocation-free: device globals)
__device__ __align__(128) float g_x  [N_NODES * HPAD];  // layer-1 features (padded)
__device__ __align__(128) float g_y  [N_NODES * HPAD];  // y = ns*relu(agg1*nd+b1)
__device__ __align__(128) float g_agg[N_NODES * HPAD];  // gather-2 result (pre-W2)
__device__ int   g_deg_out[N_NODES];
__device__ int   g_cnt[N_NODES];            // in-degree, built by k_fill
__device__ __align__(16) int g_ell[N_NODES * ELL_CAP];  // ELL adjacency

// Weights in constant memory
__constant__ float cW1[F_IN * HDIM];
__constant__ float cW2[HDIM * HDIM];
__constant__ float cWd[4 * HDIM];
__constant__ float cb1[HDIM];
__constant__ float cb2[HDIM];
__constant__ float cbd[1];

// ---------------------------------------------------------------------------
// Out-degree count (feature chain, side stream)
__global__ void k_count_out(const int* __restrict__ src) {
    int i = blockIdx.x * blockDim.x + threadIdx.x;
    if (i >= N_EDGES / 4) return;
    int4 s = __ldg(reinterpret_cast<const int4*>(src) + i);
    atomicAdd(&g_deg_out[s.x], 1);
    atomicAdd(&g_deg_out[s.y], 1);
    atomicAdd(&g_deg_out[s.z], 1);
    atomicAdd(&g_deg_out[s.w], 1);
}

// ELL fill: counts in-degree AND places edges in one pass. No scan needed.
__global__ void k_fill(const int* __restrict__ src, const int* __restrict__ dst) {
    int i = blockIdx.x * blockDim.x + threadIdx.x;
    if (i >= N_EDGES / 4) return;
    int4 s = __ldg(reinterpret_cast<const int4*>(src) + i);
    int4 d = __ldg(reinterpret_cast<const int4*>(dst) + i);
    int p0 = atomicAdd(&g_cnt[d.x], 1);
    int p1 = atomicAdd(&g_cnt[d.y], 1);
    int p2 = atomicAdd(&g_cnt[d.z], 1);
    int p3 = atomicAdd(&g_cnt[d.w], 1);
    g_ell[(d.x << 6) + p0] = s.x;
    g_ell[(d.y << 6) + p1] = s.y;
    g_ell[(d.z << 6) + p2] = s.z;
    g_ell[(d.w << 6) + p3] = s.w;
}

// ---------------------------------------------------------------------------
// x = ns * (features @ W1), written to padded (stride-32) rows
__global__ void __launch_bounds__(256) k_transform1(const float* __restrict__ feats) {
    int n = blockIdx.x * blockDim.x + threadIdx.x;
    if (n >= N_NODES) return;

    const float4* frow = reinterpret_cast<const float4*>(feats + (size_t)n * F_IN);
    float4 f[8];
#pragma unroll
    for (int i = 0; i < 8; i++) f[i] = __ldg(frow + i);

    float ns = rsqrtf(fmaxf((float)g_deg_out[n], 1.0f));

    float acc[HDIM];
#pragma unroll
    for (int j = 0; j < HDIM; j++) acc[j] = 0.0f;

    const float* fv = reinterpret_cast<const float*>(f);
#pragma unroll
    for (int k = 0; k < F_IN; k++) {
        float x = fv[k];
#pragma unroll
        for (int j = 0; j < HDIM; j++) acc[j] = fmaf(x, cW1[k * HDIM + j], acc[j]);
    }

    float4* orow = reinterpret_cast<float4*>(g_x + (size_t)n * HPAD);
#pragma unroll
    for (int j4 = 0; j4 < HDIM / 4; j4++)
        orow[j4] = make_float4(acc[4*j4] * ns, acc[4*j4+1] * ns,
                               acc[4*j4+2] * ns, acc[4*j4+3] * ns);
}

// Gather core: 6 lanes/node, int4 index blocks, padded single-line rows.
__device__ __forceinline__ float4 gather_row(const float4* __restrict__ x4,
                                             const int* __restrict__ idx,
                                             int deg, int j) {
    float4 acc = make_float4(0.f, 0.f, 0.f, 0.f);
    const int4* idx4 = reinterpret_cast<const int4*>(idx);
    int nb = deg >> 2;
    for (int b = 0; b < nb; b++) {
        int4 si = __ldg(idx4 + b);
        float4 v0 = __ldg(x4 + (size_t)si.x * 8 + j);
        float4 v1 = __ldg(x4 + (size_t)si.y * 8 + j);
        float4 v2 = __ldg(x4 + (size_t)si.z * 8 + j);
        float4 v3 = __ldg(x4 + (size_t)si.w * 8 + j);
        acc.x += (v0.x + v1.x) + (v2.x + v3.x);
        acc.y += (v0.y + v1.y) + (v2.y + v3.y);
        acc.z += (v0.z + v1.z) + (v2.z + v3.z);
        acc.w += (v0.w + v1.w) + (v2.w + v3.w);
    }
    for (int e = nb << 2; e < deg; e++) {
        int s = __ldg(idx + e);
        float4 v = __ldg(x4 + (size_t)s * 8 + j);
        acc.x += v.x; acc.y += v.y; acc.z += v.z; acc.w += v.w;
    }
    return acc;
}

// Gather #1 + barrier-free epilogue: y[n] = ns*relu(agg*nd + b1)
__global__ void __launch_bounds__(192) k_gather_y() {
    int t = blockIdx.x * 192 + threadIdx.x;
    int node = t / 6;
    int j = t - node * 6;
    if (node >= N_NODES) return;

    int deg = __ldg(&g_cnt[node]);
    float4 acc = gather_row(reinterpret_cast<const float4*>(g_x),
                            g_ell + (node << 6), deg, j);

    float nd = rsqrtf(fmaxf((float)deg, 1.0f));
    float ns = rsqrtf(fmaxf((float)__ldg(&g_deg_out[node]), 1.0f));
    const float4 b = reinterpret_cast<const float4*>(cb1)[j];

    float4 y;
    y.x = ns * fmaxf(fmaf(acc.x, nd, b.x), 0.0f);
    y.y = ns * fmaxf(fmaf(acc.y, nd, b.y), 0.0f);
    y.z = ns * fmaxf(fmaf(acc.z, nd, b.z), 0.0f);
    y.w = ns * fmaxf(fmaf(acc.w, nd, b.w), 0.0f);
    reinterpret_cast<float4*>(g_y)[(size_t)node * 8 + j] = y;
}

// Gather #2: agg[n] = sum y[s]
__global__ void __launch_bounds__(192) k_gather2() {
    int t = blockIdx.x * 192 + threadIdx.x;
    int node = t / 6;
    int j = t - node * 6;
    if (node >= N_NODES) return;

    int deg = __ldg(&g_cnt[node]);
    float4 acc = gather_row(reinterpret_cast<const float4*>(g_y),
                            g_ell + (node << 6), deg, j);

    reinterpret_cast<float4*>(g_agg)[(size_t)node * 8 + j] = acc;
}

// Final: t = agg @ W2 (commuted), h2 = relu(t*nd + b2), grouped readout.
__global__ void __launch_bounds__(256) k_final(float* __restrict__ out) {
    int n = blockIdx.x * blockDim.x + threadIdx.x;
    if (n >= N_NODES) return;

    const float4* arow = reinterpret_cast<const float4*>(g_agg + (size_t)n * HPAD);
    float4 a[6];
#pragma unroll
    for (int i = 0; i < 6; i++) a[i] = __ldg(arow + i);
    const float* r = reinterpret_cast<const float*>(a);

    float tacc[HDIM];
#pragma unroll
    for (int j = 0; j < HDIM; j++) tacc[j] = 0.0f;
#pragma unroll
    for (int k = 0; k < HDIM; k++) {
        float rk = r[k];
#pragma unroll
        for (int j = 0; j < HDIM; j++) tacc[j] = fmaf(rk, cW2[k * HDIM + j], tacc[j]);
    }

    float nd = rsqrtf(fmaxf((float)g_cnt[n], 1.0f));
    int k = n & 3;

    float partial = 0.0f;
#pragma unroll
    for (int j = 0; j < HDIM; j++)
        partial = fmaf(fmaxf(fmaf(tacc[j], nd, cb2[j]), 0.0f), cWd[k * HDIM + j], partial);

    partial += __shfl_xor_sync(0xFFFFFFFFu, partial, 1);
    partial += __shfl_xor_sync(0xFFFFFFFFu, partial, 2);
    if (k == 0) out[n >> 2] = partial + cbd[0];
}

// ---------------------------------------------------------------------------
extern "C" void kernel_launch(void* const* d_in, const int* in_sizes, int n_in,
                              void* d_out, int out_size) {
    const float* feats = (const float*)d_in[0];
    const int*   src   = (const int*)  d_in[1];
    const int*   dst   = (const int*)  d_in[2];
    float* out = (float*)d_out;

    // Lazy one-time handles (created on the correctness call, before capture).
    static cudaStream_t s1 = nullptr;
    static cudaEvent_t ev_fork = nullptr, ev_join = nullptr;
    if (s1 == nullptr) {
        cudaStreamCreateWithFlags(&s1, cudaStreamNonBlocking);
        cudaEventCreateWithFlags(&ev_fork, cudaEventDisableTiming);
        cudaEventCreateWithFlags(&ev_join, cudaEventDisableTiming);
    }

    void *p_dout, *p_cnt;
    cudaGetSymbolAddress(&p_dout, g_deg_out);
    cudaGetSymbolAddress(&p_cnt, g_cnt);

    // Prologue on the main (captured) stream
    cudaMemsetAsync(p_cnt, 0, sizeof(int) * N_NODES);
    cudaMemsetAsync(p_dout, 0, sizeof(int) * N_NODES);
    cudaMemcpyToSymbolAsync(cW1, d_in[3], sizeof(float) * F_IN * HDIM, 0, cudaMemcpyDeviceToDevice);
    cudaMemcpyToSymbolAsync(cb1, d_in[4], sizeof(float) * HDIM, 0, cudaMemcpyDeviceToDevice);
    cudaMemcpyToSymbolAsync(cW2, d_in[5], sizeof(float) * HDIM * HDIM, 0, cudaMemcpyDeviceToDevice);
    cudaMemcpyToSymbolAsync(cb2, d_in[6], sizeof(float) * HDIM, 0, cudaMemcpyDeviceToDevice);
    cudaMemcpyToSymbolAsync(cWd, d_in[7], sizeof(float) * 4 * HDIM, 0, cudaMemcpyDeviceToDevice);
    cudaMemcpyToSymbolAsync(cbd, d_in[8], sizeof(float), 0, cudaMemcpyDeviceToDevice);

    const int T = 256;
    int gN = (N_NODES + T - 1) / T;
    int gC = (N_EDGES / 4 + T - 1) / T;
    int gG = (N_NODES * 6 + 191) / 192;

    // Fork: side stream runs the feature chain (count_out -> transform1)
    cudaEventRecord(ev_fork, 0);
    cudaStreamWaitEvent(s1, ev_fork, 0);
    k_count_out<<<gC, T, 0, s1>>>(src);
    k_transform1<<<gN, T, 0, s1>>>(feats);
    cudaEventRecord(ev_join, s1);

    // Main stream: single-pass ELL build (count + place fused)
    k_fill<<<gC, T>>>(src, dst);

    // Join, then the serial tail
    cudaStreamWaitEvent(0, ev_join, 0);
    k_gather_y<<<gG, 192>>>();
    k_gather2<<<gG, 192>>>();
    k_final<<<gN, T>>>(out);
}

// round 16
// speedup vs baseline: 1.0518x; 1.0518x over previous
#include <cuda_runtime.h>

#define N_NODES 200000
#define N_EDGES 1600000
#define F_IN    32
#define HDIM    24
#define ELL_CAP 64             // max in-degree capacity (Poisson(8): P(>64) ~ 0)

// Scratch (allocation-free: device globals)
__device__ float g_x  [N_NODES * HDIM];   // layer-1 transformed features
__device__ float g_y  [N_NODES * HDIM];   // y = ns * relu(agg1*nd + b1)
__device__ float g_agg[N_NODES * HDIM];   // gather-2 result (pre-W2)
__device__ int   g_deg_out[N_NODES];
__device__ int   g_cnt[N_NODES];          // in-degree, built by k_fill
__device__ __align__(16) int g_ell[N_NODES * ELL_CAP];  // ELL adjacency

// Weights in constant memory
__constant__ float cW1[F_IN * HDIM];
__constant__ float cW2[HDIM * HDIM];
__constant__ float cWd[4 * HDIM];
__constant__ float cb1[HDIM];
__constant__ float cb2[HDIM];
__constant__ float cbd[1];

// ---------------------------------------------------------------------------
// Out-degree count (feature chain, side stream)
__global__ void k_count_out(const int* __restrict__ src) {
    int i = blockIdx.x * blockDim.x + threadIdx.x;
    if (i >= N_EDGES / 4) return;
    int4 s = __ldg(reinterpret_cast<const int4*>(src) + i);
    atomicAdd(&g_deg_out[s.x], 1);
    atomicAdd(&g_deg_out[s.y], 1);
    atomicAdd(&g_deg_out[s.z], 1);
    atomicAdd(&g_deg_out[s.w], 1);
}

// ELL fill: counts in-degree AND places edges in one pass. No scan needed.
__global__ void k_fill(const int* __restrict__ src, const int* __restrict__ dst) {
    int i = blockIdx.x * blockDim.x + threadIdx.x;
    if (i >= N_EDGES / 4) return;
    int4 s = __ldg(reinterpret_cast<const int4*>(src) + i);
    int4 d = __ldg(reinterpret_cast<const int4*>(dst) + i);
    int p0 = atomicAdd(&g_cnt[d.x], 1);
    int p1 = atomicAdd(&g_cnt[d.y], 1);
    int p2 = atomicAdd(&g_cnt[d.z], 1);
    int p3 = atomicAdd(&g_cnt[d.w], 1);
    g_ell[(d.x << 6) + p0] = s.x;
    g_ell[(d.y << 6) + p1] = s.y;
    g_ell[(d.z << 6) + p2] = s.z;
    g_ell[(d.w << 6) + p3] = s.w;
}

// ---------------------------------------------------------------------------
// x = ns * (features @ W1)
__global__ void __launch_bounds__(256) k_transform1(const float* __restrict__ feats) {
    int n = blockIdx.x * blockDim.x + threadIdx.x;
    if (n >= N_NODES) return;

    const float4* frow = reinterpret_cast<const float4*>(feats + (size_t)n * F_IN);
    float4 f[8];
#pragma unroll
    for (int i = 0; i < 8; i++) f[i] = __ldg(frow + i);

    float ns = rsqrtf(fmaxf((float)g_deg_out[n], 1.0f));

    float acc[HDIM];
#pragma unroll
    for (int j = 0; j < HDIM; j++) acc[j] = 0.0f;

    const float* fv = reinterpret_cast<const float*>(f);
#pragma unroll
    for (int k = 0; k < F_IN; k++) {
        float x = fv[k];
#pragma unroll
        for (int j = 0; j < HDIM; j++) acc[j] = fmaf(x, cW1[k * HDIM + j], acc[j]);
    }

    float4* orow = reinterpret_cast<float4*>(g_x + (size_t)n * HDIM);
#pragma unroll
    for (int j4 = 0; j4 < HDIM / 4; j4++)
        orow[j4] = make_float4(acc[4*j4] * ns, acc[4*j4+1] * ns,
                               acc[4*j4+2] * ns, acc[4*j4+3] * ns);
}

// Gather core: 6 lanes/node, int4 index blocks (1 LDG per 4 edges), stride-24 rows
__device__ __forceinline__ float4 gather_row(const float4* __restrict__ x4,
                                             const int* __restrict__ idx,
                                             int deg, int j) {
    float4 acc = make_float4(0.f, 0.f, 0.f, 0.f);
    const int4* idx4 = reinterpret_cast<const int4*>(idx);
    int nb = deg >> 2;
    for (int b = 0; b < nb; b++) {
        int4 si = __ldg(idx4 + b);
        float4 v0 = __ldg(x4 + (size_t)si.x * 6 + j);
        float4 v1 = __ldg(x4 + (size_t)si.y * 6 + j);
        float4 v2 = __ldg(x4 + (size_t)si.z * 6 + j);
        float4 v3 = __ldg(x4 + (size_t)si.w * 6 + j);
        acc.x += (v0.x + v1.x) + (v2.x + v3.x);
        acc.y += (v0.y + v1.y) + (v2.y + v3.y);
        acc.z += (v0.z + v1.z) + (v2.z + v3.z);
        acc.w += (v0.w + v1.w) + (v2.w + v3.w);
    }
    for (int e = nb << 2; e < deg; e++) {
        int s = __ldg(idx + e);
        float4 v = __ldg(x4 + (size_t)s * 6 + j);
        acc.x += v.x; acc.y += v.y; acc.z += v.z; acc.w += v.w;
    }
    return acc;
}

// Gather #1 + barrier-free epilogue: y[n] = ns*relu(agg*nd + b1)
__global__ void __launch_bounds__(192) k_gather_y() {
    int t = blockIdx.x * 192 + threadIdx.x;
    int node = t / 6;
    int j = t - node * 6;
    if (node >= N_NODES) return;

    int deg = __ldg(&g_cnt[node]);
    float4 acc = gather_row(reinterpret_cast<const float4*>(g_x),
                            g_ell + (node << 6), deg, j);

    float nd = rsqrtf(fmaxf((float)deg, 1.0f));
    float ns = rsqrtf(fmaxf((float)__ldg(&g_deg_out[node]), 1.0f));
    const float4 b = reinterpret_cast<const float4*>(cb1)[j];

    float4 y;
    y.x = ns * fmaxf(fmaf(acc.x, nd, b.x), 0.0f);
    y.y = ns * fmaxf(fmaf(acc.y, nd, b.y), 0.0f);
    y.z = ns * fmaxf(fmaf(acc.z, nd, b.z), 0.0f);
    y.w = ns * fmaxf(fmaf(acc.w, nd, b.w), 0.0f);
    reinterpret_cast<float4*>(g_y)[(size_t)node * 6 + j] = y;
}

// Gather #2: agg[n] = sum y[s]
__global__ void __launch_bounds__(192) k_gather2() {
    int t = blockIdx.x * 192 + threadIdx.x;
    int node = t / 6;
    int j = t - node * 6;
    if (node >= N_NODES) return;

    int deg = __ldg(&g_cnt[node]);
    float4 acc = gather_row(reinterpret_cast<const float4*>(g_y),
                            g_ell + (node << 6), deg, j);

    reinterpret_cast<float4*>(g_agg)[(size_t)node * 6 + j] = acc;
}

// Final: t = agg @ W2 (commuted), h2 = relu(t*nd + b2), grouped readout.
__global__ void __launch_bounds__(256) k_final(float* __restrict__ out) {
    int n = blockIdx.x * blockDim.x + threadIdx.x;
    if (n >= N_NODES) return;

    const float4* arow = reinterpret_cast<const float4*>(g_agg + (size_t)n * HDIM);
    float4 a[6];
#pragma unroll
    for (int i = 0; i < 6; i++) a[i] = __ldg(arow + i);
    const float* r = reinterpret_cast<const float*>(a);

    float tacc[HDIM];
#pragma unroll
    for (int j = 0; j < HDIM; j++) tacc[j] = 0.0f;
#pragma unroll
    for (int k = 0; k < HDIM; k++) {
        float rk = r[k];
#pragma unroll
        for (int j = 0; j < HDIM; j++) tacc[j] = fmaf(rk, cW2[k * HDIM + j], tacc[j]);
    }

    float nd = rsqrtf(fmaxf((float)g_cnt[n], 1.0f));
    int k = n & 3;

    float partial = 0.0f;
#pragma unroll
    for (int j = 0; j < HDIM; j++)
        partial = fmaf(fmaxf(fmaf(tacc[j], nd, cb2[j]), 0.0f), cWd[k * HDIM + j], partial);

    partial += __shfl_xor_sync(0xFFFFFFFFu, partial, 1);
    partial += __shfl_xor_sync(0xFFFFFFFFu, partial, 2);
    if (k == 0) out[n >> 2] = partial + cbd[0];
}

// ---------------------------------------------------------------------------
extern "C" void kernel_launch(void* const* d_in, const int* in_sizes, int n_in,
                              void* d_out, int out_size) {
    const float* feats = (const float*)d_in[0];
    const int*   src   = (const int*)  d_in[1];
    const int*   dst   = (const int*)  d_in[2];
    float* out = (float*)d_out;

    // Lazy one-time handles (created on the correctness call, before capture).
    static cudaStream_t s1 = nullptr, s2 = nullptr;
    static cudaEvent_t ev_fork = nullptr, ev1 = nullptr, ev2 = nullptr;
    if (s1 == nullptr) {
        cudaStreamCreateWithFlags(&s1, cudaStreamNonBlocking);
        cudaStreamCreateWithFlags(&s2, cudaStreamNonBlocking);
        cudaEventCreateWithFlags(&ev_fork, cudaEventDisableTiming);
        cudaEventCreateWithFlags(&ev1, cudaEventDisableTiming);
        cudaEventCreateWithFlags(&ev2, cudaEventDisableTiming);
    }

    void *p_dout, *p_cnt;
    cudaGetSymbolAddress(&p_dout, g_deg_out);
    cudaGetSymbolAddress(&p_cnt, g_cnt);

    const int T = 256;
    int gN = (N_NODES + T - 1) / T;
    int gC = (N_EDGES / 4 + T - 1) / T;
    int gG = (N_NODES * 6 + 191) / 192;

    // Fork immediately
    cudaEventRecord(ev_fork, 0);
    cudaStreamWaitEvent(s1, ev_fork, 0);
    cudaStreamWaitEvent(s2, ev_fork, 0);

    // s1: feature chain (W1/b1 copies -> deg_out zero -> count_out -> transform1)
    cudaMemcpyToSymbolAsync(cW1, d_in[3], sizeof(float) * F_IN * HDIM, 0,
                            cudaMemcpyDeviceToDevice, s1);
    cudaMemcpyToSymbolAsync(cb1, d_in[4], sizeof(float) * HDIM, 0,
                            cudaMemcpyDeviceToDevice, s1);
    cudaMemsetAsync(p_dout, 0, sizeof(int) * N_NODES, s1);
    k_count_out<<<gC, T, 0, s1>>>(src);
    k_transform1<<<gN, T, 0, s1>>>(feats);
    cudaEventRecord(ev1, s1);

    // s2: tail weights (needed only after the join)
    cudaMemcpyToSymbolAsync(cW2, d_in[5], sizeof(float) * HDIM * HDIM, 0,
                            cudaMemcpyDeviceToDevice, s2);
    cudaMemcpyToSymbolAsync(cb2, d_in[6], sizeof(float) * HDIM, 0,
                            cudaMemcpyDeviceToDevice, s2);
    cudaMemcpyToSymbolAsync(cWd, d_in[7], sizeof(float) * 4 * HDIM, 0,
                            cudaMemcpyDeviceToDevice, s2);
    cudaMemcpyToSymbolAsync(cbd, d_in[8], sizeof(float), 0,
                            cudaMemcpyDeviceToDevice, s2);
    cudaEventRecord(ev2, s2);

    // main: ELL build
    cudaMemsetAsync(p_cnt, 0, sizeof(int) * N_NODES);
    k_fill<<<gC, T>>>(src, dst);

    // Join, then the serial tail
    cudaStreamWaitEvent(0, ev1, 0);
    cudaStreamWaitEvent(0, ev2, 0);
    k_gather_y<<<gG, 192>>>();
    k_gather2<<<gG, 192>>>();
    k_final<<<gN, T>>>(out);
}